// round 11
// baseline (speedup 1.0000x reference)
#include <cuda_runtime.h>
#include <cstdint>

#define DIMX   1024
#define NH     16
#define HDIM   64
#define LAT    128
#define QRANK  256
#define BATCH  4
#define SEQ    2048
#define MTOT   (BATCH*SEQ)   // 8192

// ---------------- scratch (device globals: no allocation allowed) -----------
__device__ float g_xtf[(size_t)MTOT * DIMX];         // tf32-rounded x
__device__ float g_cq [(size_t)MTOT * 384];          // [kv_latent | qc] fused
__device__ float g_kv [(size_t)MTOT * 2 * DIMX];     // [K | V] per row
__device__ float g_q  [(size_t)MTOT * DIMX];
__device__ float g_ctx[(size_t)MTOT * DIMX];
__device__ float g_vt [(size_t)BATCH * DIMX * SEQ];  // V^T per batch: [b][d][s]
__device__ float g_wT [1966080];                     // transposed+rounded weights
__device__ float g_bias[384];                        // [b_kvc | b_qc]

#define WT_KVC 0          // [128][1024]
#define WT_QC  131072     // [256][1024]
#define WT_KVU 393216     // [2048][128]
#define WT_QU  655360     // [1024][256]
#define WT_O   917504     // [1024][1024]

// ---------------- helpers ----------------------------------------------------
__device__ __forceinline__ unsigned f2tf(float x){
    unsigned r; asm("cvt.rna.tf32.f32 %0, %1;" : "=r"(r) : "f"(x)); return r;
}
__device__ __forceinline__ float f2tff(float x){ return __uint_as_float(f2tf(x)); }
__device__ __forceinline__ void ldsm4(unsigned* r, unsigned a){
    asm volatile("ldmatrix.sync.aligned.m8n8.x4.shared.b16 {%0,%1,%2,%3}, [%4];"
        : "=r"(r[0]), "=r"(r[1]), "=r"(r[2]), "=r"(r[3]) : "r"(a));
}
__device__ __forceinline__ void mma8(float* c, const unsigned* a, const unsigned* b){
    asm volatile("mma.sync.aligned.m16n8k8.row.col.f32.tf32.tf32.f32 "
        "{%0,%1,%2,%3}, {%4,%5,%6,%7}, {%8,%9}, {%0,%1,%2,%3};"
        : "+f"(c[0]), "+f"(c[1]), "+f"(c[2]), "+f"(c[3])
        : "r"(a[0]), "r"(a[1]), "r"(a[2]), "r"(a[3]), "r"(b[0]), "r"(b[1]));
}
__device__ __forceinline__ void cpa16(unsigned d, const void* s){
    asm volatile("cp.async.cg.shared.global [%0], [%1], 16;" :: "r"(d), "l"(s));
}
__device__ __forceinline__ void cpa_commit(){ asm volatile("cp.async.commit_group;"); }
template<int N> __device__ __forceinline__ void cpa_wait(){
    asm volatile("cp.async.wait_group %0;" :: "n"(N));
}

// swizzled float-index: tile row stride 32 floats (8 chunks of 16B)
#define SWZ32(r,c) (((r)<<5) + ((((c) ^ ((r)&7)) & 7) << 2))
// tile row stride 64 floats (16 chunks)
#define SWZ64(r,c) (((r)<<6) + (((((c)&8) | (((c) ^ (r)) & 7))) << 2))

// 0.125 * log2(e): folds the 1/sqrt(64) score scale into exp2
#define SM_C 0.18033688011112042f

// ---------------- elementwise tf32 rounding of x -----------------------------
__global__ void cvt_tf32_kernel(const float* __restrict__ in, float* __restrict__ out, int n4)
{
    int i = blockIdx.x*blockDim.x + threadIdx.x;
    for (; i < n4; i += gridDim.x*blockDim.x){
        float4 v = ((const float4*)in)[i];
        ((float4*)out)[i] = make_float4(f2tff(v.x), f2tff(v.y), f2tff(v.z), f2tff(v.w));
    }
}

__global__ void concat_bias_kernel(const float* __restrict__ b1, const float* __restrict__ b2,
                                   float* __restrict__ o)
{
    int t = threadIdx.x;
    o[t] = (t < 128) ? b1[t] : b2[t-128];
}

// ---------------- batched transpose + tf32 round ----------------------------
__global__ void transpose_kernel(const float* __restrict__ in, float* __restrict__ out,
                                 int R, int C, int ics, size_t ibs, size_t obs)
{
    __shared__ float t[32][33];
    const float* ib = in  + blockIdx.z * ibs;
    float*       ob = out + blockIdx.z * obs;
    int r0 = blockIdx.y * 32, c0 = blockIdx.x * 32;
    int tx = threadIdx.x, ty = threadIdx.y;
#pragma unroll
    for (int i = 0; i < 32; i += 8)
        t[ty + i][tx] = ib[(size_t)(r0 + ty + i) * ics + c0 + tx];
    __syncthreads();
#pragma unroll
    for (int i = 0; i < 32; i += 8)
        ob[(size_t)(c0 + ty + i) * R + r0 + tx] = f2tff(t[tx][ty + i]);
}

// ---------------- tf32 mma GEMM, 3-stage cp.async pipeline -------------------
// C[.,N] = A @ Bt^T + bias. A lda-strided, Bt compact [N][K]. Operands already
// tf32-rounded in gmem. BM=BN=128, BK=32, 256 threads, warp tile 64x32.
template<int ROUND>
__global__ __launch_bounds__(256)
void gemm_mma(const float* __restrict__ A, const float* __restrict__ Bt,
              const float* __restrict__ bias, float* __restrict__ C,
              int N, int K, int lda, int ldc)
{
    extern __shared__ float sm[];
    float* As = sm;            // 3 stages x 4096 floats
    float* Bs = sm + 3*4096;
    const int tid  = threadIdx.x;
    const int lane = tid & 31, warp = tid >> 5;
    const int wm = warp >> 2, wn = warp & 3;
    const int m0 = blockIdx.y * 128, n0 = blockIdx.x * 128;
    const unsigned sA = (unsigned)__cvta_generic_to_shared(As);
    const unsigned sB = (unsigned)__cvta_generic_to_shared(Bs);
    const int lrow = tid >> 3, lc4 = tid & 7;
    const int g = lane >> 2, t4 = lane & 3;
    const int ar = lane & 15, asel = lane >> 4;

    auto load_stage = [&](int st, int k0){
#pragma unroll
        for (int i = 0; i < 4; i++){
            int r = lrow + 32*i;
            cpa16(sA + 4*(st*4096 + SWZ32(r, lc4)), A  + (size_t)(m0 + r)*lda + k0 + 4*lc4);
            cpa16(sB + 4*(st*4096 + SWZ32(r, lc4)), Bt + (size_t)(n0 + r)*K   + k0 + 4*lc4);
        }
        cpa_commit();
    };

    const int T = K >> 5;
    load_stage(0, 0);
    if (T > 1) load_stage(1, 32);

    float cacc[4][4][4];
#pragma unroll
    for (int i = 0; i < 4; i++)
#pragma unroll
        for (int j = 0; j < 4; j++)
#pragma unroll
            for (int v = 0; v < 4; v++) cacc[i][j][v] = 0.f;

    for (int it = 0; it < T; it++){
        if (it + 1 < T) cpa_wait<1>(); else cpa_wait<0>();
        __syncthreads();
        if (it + 2 < T) load_stage((it+2)%3, 32*(it+2));
        const int so = (it%3)*4096;
#pragma unroll
        for (int kk = 0; kk < 4; kk++){
            unsigned af[4][4];
#pragma unroll
            for (int mi = 0; mi < 4; mi++)
                ldsm4(af[mi], sA + 4*(so + SWZ32(64*wm + 16*mi + ar, 2*kk + asel)));
            unsigned bt[2][4];
#pragma unroll
            for (int p = 0; p < 2; p++){
                int brow = 32*wn + 8*(2*p + (lane >> 4)) + (lane & 7);
                int bch  = 2*kk + ((lane >> 3) & 1);
                ldsm4(bt[p], sB + 4*(so + SWZ32(brow, bch)));
            }
#pragma unroll
            for (int mi = 0; mi < 4; mi++)
#pragma unroll
                for (int nj = 0; nj < 4; nj++)
                    mma8(cacc[mi][nj], af[mi], &bt[nj >> 1][2*(nj & 1)]);
        }
        __syncthreads();
    }
    // epilogue: += bias; optionally round to tf32 for downstream MMA consumers
#pragma unroll
    for (int mi = 0; mi < 4; mi++){
        int row = m0 + 64*wm + 16*mi + g;
#pragma unroll
        for (int nj = 0; nj < 4; nj++){
            int col = n0 + 32*wn + 8*nj + 2*t4;
            float2 b2 = *(const float2*)(bias + col);
            float v0 = cacc[mi][nj][0] + b2.x, v1 = cacc[mi][nj][1] + b2.y;
            float v2 = cacc[mi][nj][2] + b2.x, v3 = cacc[mi][nj][3] + b2.y;
            if (ROUND){ v0=f2tff(v0); v1=f2tff(v1); v2=f2tff(v2); v3=f2tff(v3); }
            *(float2*)(C + (size_t)row*ldc + col)       = make_float2(v0, v1);
            *(float2*)(C + (size_t)(row + 8)*ldc + col) = make_float2(v2, v3);
        }
    }
}

// ---------------- tf32 mma flash attention (causal, hd=64) ------------------
// 256 threads = 8 warps; warp w owns q rows 16w..16w+15. BM=128, BN=64.
// K/V double-buffered via cp.async; Q smem buffer reused for P.
// minBlocksPerMultiprocessor=2: cap regs at 128 so two CTAs interleave
// softmax (MUFU/shuffle) of one with mma bursts of the other.
__global__ __launch_bounds__(256, 2)
void flash_mma(const float* __restrict__ Qm, const float* __restrict__ KVm,
               const float* __restrict__ Vt, float* __restrict__ Om)
{
    extern __shared__ float sm[];
    float* sQP = sm;              // 128*64 = 8192 floats
    float* sK  = sm + 8192;       // 2 stages x 4096
    float* sV  = sm + 16384;      // 2 stages x 4096
    const int tid  = threadIdx.x;
    const int lane = tid & 31, w = tid >> 5;
    const int g = lane >> 2, t4 = lane & 3;
    const int qt = (gridDim.x - 1) - blockIdx.x;   // largest-work blocks first
    const int q0 = qt << 7;
    const int h  = blockIdx.y;
    const int b  = blockIdx.z;

    const unsigned sQPa = (unsigned)__cvta_generic_to_shared(sQP);
    const unsigned sKa  = (unsigned)__cvta_generic_to_shared(sK);
    const unsigned sVa  = (unsigned)__cvta_generic_to_shared(sV);

    const float* Qg = Qm  + ((size_t)(b*SEQ + q0))*DIMX + h*HDIM;
    const float* Kg = KVm + ((size_t)(b*SEQ))*(2*DIMX)  + h*HDIM;
    const float* Vg = Vt  + ((size_t)(b*DIMX + h*HDIM))*SEQ;

    auto load_kv = [&](int st, int k0){
#pragma unroll
        for (int i = 0; i < 4; i++){
            int lin = tid + (i << 8);
            int r = lin >> 4, c4 = lin & 15;
            cpa16(sKa + 4*(st*4096 + SWZ64(r, c4)), Kg + (size_t)(k0 + r)*(2*DIMX) + (c4 << 2));
            cpa16(sVa + 4*(st*4096 + SWZ64(r, c4)), Vg + (size_t)r*SEQ + k0 + (c4 << 2));
        }
        cpa_commit();
    };

    // Q tile; already tf32 in gmem
#pragma unroll
    for (int i = 0; i < 8; i++){
        int lin = tid + (i << 8);
        int r = lin >> 4, c4 = lin & 15;
        cpa16(sQPa + 4*SWZ64(r, c4), Qg + (size_t)r*DIMX + (c4 << 2));
    }
    cpa_commit();
    load_kv(0, 0);

    cpa_wait<1>();       // Q group complete (KV0 may still be in flight)
    __syncthreads();

    // Q fragments -> registers (16 rows x 64 d per warp)
    unsigned qf[8][4];
#pragma unroll
    for (int kk = 0; kk < 8; kk++)
        ldsm4(qf[kk], sQPa + 4*SWZ64(16*w + (lane & 15), 2*kk + (lane >> 4)));

    float m_i[2] = {-1e30f, -1e30f}, l_i[2] = {0.f, 0.f};
    float oacc[8][4];
#pragma unroll
    for (int j = 0; j < 8; j++)
#pragma unroll
        for (int v = 0; v < 4; v++) oacc[j][v] = 0.f;

    const int row0 = q0 + 16*w + g;
    const int nt = 2*qt + 2;
    for (int kt = 0; kt < nt; kt++){
        const int k0 = kt << 6;
        cpa_wait<0>();
        __syncthreads();     // all warps done with previous stage + P/Q buffer
        if (kt + 1 < nt) load_kv((kt+1) & 1, (kt+1) << 6);
        const int so = (kt & 1) * 4096;

        // S = Q K^T : warp tile 16 x 64 (raw scores; 1/8 scale folded into exp2)
        float sacc[8][4];
#pragma unroll
        for (int j = 0; j < 8; j++)
#pragma unroll
            for (int v = 0; v < 4; v++) sacc[j][v] = 0.f;
#pragma unroll
        for (int kk = 0; kk < 8; kk++){
            unsigned bt[4][4];
#pragma unroll
            for (int p = 0; p < 4; p++){
                int brow = 8*(2*p + (lane >> 4)) + (lane & 7);
                int bch  = 2*kk + ((lane >> 3) & 1);
                ldsm4(bt[p], sKa + 4*(so + SWZ64(brow, bch)));
            }
#pragma unroll
            for (int j = 0; j < 8; j++)
                mma8(sacc[j], qf[kk], &bt[j >> 1][2*(j & 1)]);
        }

        // causal mask (only tiles crossing this warp's rows)
        if (k0 + 63 > row0){
#pragma unroll
            for (int j = 0; j < 8; j++){
                int c = k0 + 8*j + 2*t4;
                if (c     > row0)     sacc[j][0] = -1e30f;
                if (c + 1 > row0)     sacc[j][1] = -1e30f;
                if (c     > row0 + 8) sacc[j][2] = -1e30f;
                if (c + 1 > row0 + 8) sacc[j][3] = -1e30f;
            }
        }

        // online softmax per row-half (rows row0, row0+8), reduce over 4 lanes.
        // weights = exp2((s - m) * SM_C): the 0.125 score scale and the
        // log2(e) of expf are folded into one constant.
#pragma unroll
        for (int hf = 0; hf < 2; hf++){
            float mx = -1e30f;
#pragma unroll
            for (int j = 0; j < 8; j++)
                mx = fmaxf(mx, fmaxf(sacc[j][2*hf], sacc[j][2*hf + 1]));
            mx = fmaxf(mx, __shfl_xor_sync(0xffffffffu, mx, 1));
            mx = fmaxf(mx, __shfl_xor_sync(0xffffffffu, mx, 2));
            float mn = fmaxf(m_i[hf], mx);
            float al = exp2f((m_i[hf] - mn) * SM_C);
            m_i[hf] = mn;
            float rs = 0.f;
#pragma unroll
            for (int j = 0; j < 8; j++){
                sacc[j][2*hf]     = exp2f((sacc[j][2*hf]     - mn) * SM_C);
                sacc[j][2*hf + 1] = exp2f((sacc[j][2*hf + 1] - mn) * SM_C);
                rs += sacc[j][2*hf] + sacc[j][2*hf + 1];
            }
            rs += __shfl_xor_sync(0xffffffffu, rs, 1);
            rs += __shfl_xor_sync(0xffffffffu, rs, 2);
            l_i[hf] = l_i[hf]*al + rs;
#pragma unroll
            for (int j = 0; j < 8; j++){
                oacc[j][2*hf]     *= al;
                oacc[j][2*hf + 1] *= al;
            }
        }

        // write P (tf32) into sQP rows 16w..16w+15 (per-warp private rows)
#pragma unroll
        for (int j = 0; j < 8; j++){
            int col = 8*j + 2*t4;
            int ch = col >> 2, wi = col & 3;
            uint2 p0 = make_uint2(f2tf(sacc[j][0]), f2tf(sacc[j][1]));
            uint2 p1 = make_uint2(f2tf(sacc[j][2]), f2tf(sacc[j][3]));
            *(uint2*)(sQP + SWZ64(16*w + g,     ch) + wi) = p0;
            *(uint2*)(sQP + SWZ64(16*w + g + 8, ch) + wi) = p1;
        }
        __syncwarp();

        // O += P @ V
#pragma unroll
        for (int kk = 0; kk < 8; kk++){
            unsigned pf[4];
            ldsm4(pf, sQPa + 4*SWZ64(16*w + (lane & 15), 2*kk + (lane >> 4)));
            unsigned bt[4][4];
#pragma unroll
            for (int p = 0; p < 4; p++){
                int brow = 8*(2*p + (lane >> 4)) + (lane & 7);
                int bch  = 2*kk + ((lane >> 3) & 1);
                ldsm4(bt[p], sVa + 4*(so + SWZ64(brow, bch)));
            }
#pragma unroll
            for (int j = 0; j < 8; j++)
                mma8(oacc[j], pf, &bt[j >> 1][2*(j & 1)]);
        }
    }

    // epilogue: normalize, round to tf32 (consumed as MMA A by final GEMM)
    float inv0 = 1.0f / l_i[0], inv1 = 1.0f / l_i[1];
    float* Og = Om + ((size_t)(b*SEQ + q0 + 16*w + g))*DIMX + h*HDIM;
#pragma unroll
    for (int j = 0; j < 8; j++){
        int col = 8*j + 2*t4;
        *(float2*)(Og + col)          = make_float2(f2tff(oacc[j][0]*inv0), f2tff(oacc[j][1]*inv0));
        *(float2*)(Og + 8*DIMX + col) = make_float2(f2tff(oacc[j][2]*inv1), f2tff(oacc[j][3]*inv1));
    }
}

// ---------------- launch -----------------------------------------------------
extern "C" void kernel_launch(void* const* d_in, const int* in_sizes, int n_in,
                              void* d_out, int out_size)
{
    (void)in_sizes; (void)n_in; (void)out_size;
    const float* x     = (const float*)d_in[0];
    // d_in[1] = mask (causal by construction; handled analytically)
    const float* w_kvc = (const float*)d_in[2];
    const float* b_kvc = (const float*)d_in[3];
    const float* w_kvu = (const float*)d_in[4];
    const float* b_kvu = (const float*)d_in[5];
    const float* w_qc  = (const float*)d_in[6];
    const float* b_qc  = (const float*)d_in[7];
    const float* w_qu  = (const float*)d_in[8];
    const float* b_qu  = (const float*)d_in[9];
    const float* w_o   = (const float*)d_in[10];
    const float* b_o   = (const float*)d_in[11];
    float* out = (float*)d_out;

    float *xtf, *cq, *kv, *q, *ctx, *vt, *wT, *bias;
    cudaGetSymbolAddress((void**)&xtf,  g_xtf);
    cudaGetSymbolAddress((void**)&cq,   g_cq);
    cudaGetSymbolAddress((void**)&kv,   g_kv);
    cudaGetSymbolAddress((void**)&q,    g_q);
    cudaGetSymbolAddress((void**)&ctx,  g_ctx);
    cudaGetSymbolAddress((void**)&vt,   g_vt);
    cudaGetSymbolAddress((void**)&wT,   g_wT);
    cudaGetSymbolAddress((void**)&bias, g_bias);

    const int SMEM = 96*1024;
    cudaFuncSetAttribute(gemm_mma<0>, cudaFuncAttributeMaxDynamicSharedMemorySize, SMEM);
    cudaFuncSetAttribute(gemm_mma<1>, cudaFuncAttributeMaxDynamicSharedMemorySize, SMEM);
    cudaFuncSetAttribute(flash_mma,   cudaFuncAttributeMaxDynamicSharedMemorySize, SMEM);

    dim3 tb(32, 8);
    // Launch order arranged so the ncu capture window (-s 5 -c 1 => 6th launch)
    // lands on the fused GEMM instead of a transpose.
    cvt_tf32_kernel<<<2048, 256>>>(x, xtf, MTOT*DIMX/4);                                  // 0
    transpose_kernel<<<dim3(128/32, 1024/32), tb>>>(w_kvc, wT + WT_KVC, 1024, 128, 128, 0, 0);  // 1
    transpose_kernel<<<dim3(256/32, 1024/32), tb>>>(w_qc,  wT + WT_QC,  1024, 256, 256, 0, 0);  // 2
    transpose_kernel<<<dim3(2048/32, 128/32), tb>>>(w_kvu, wT + WT_KVU, 128, 2048, 2048, 0, 0); // 3
    concat_bias_kernel<<<1, 384>>>(b_kvc, b_qc, bias);                                    // 4
    // 5: fused [kv_latent | qc] = x @ [w_kvc | w_qc]^T + bias   [8192,384]  <-- profiled
    gemm_mma<1><<<dim3(3, 64), 256, SMEM>>>(xtf, wT + WT_KVC, bias, cq, 384, DIMX, DIMX, 384);
    transpose_kernel<<<dim3(1024/32, 256/32), tb>>>(w_qu,  wT + WT_QU,  256, 1024, 1024, 0, 0); // 6
    transpose_kernel<<<dim3(1024/32, 1024/32), tb>>>(w_o,  wT + WT_O,  1024, 1024, 1024, 0, 0); // 7
    // kv = kv_latent @ w_kvu^T + b_kvu                          [8192,2048]
    gemm_mma<1><<<dim3(16, 64), 256, SMEM>>>(cq, wT + WT_KVU, b_kvu, kv, 2*DIMX, LAT, 384, 2*DIMX);
    // V^T per batch
    transpose_kernel<<<dim3(1024/32, 2048/32, BATCH), tb>>>(
        kv + DIMX, vt, SEQ, DIMX, 2*DIMX, (size_t)SEQ*2*DIMX, (size_t)DIMX*SEQ);
    // Q = qc @ w_qu^T + b_qu                                    [8192,1024]
    gemm_mma<1><<<dim3(8, 64), 256, SMEM>>>(cq + 128, wT + WT_QU, b_qu, q, DIMX, QRANK, 384, DIMX);
    // attention
    flash_mma<<<dim3(SEQ/128, NH, BATCH), 256, SMEM>>>(q, kv, vt, ctx);
    // out = ctx @ w_o^T + b_o (fp32 epilogue)                   [8192,1024]
    gemm_mma<0><<<dim3(8, 64), 256, SMEM>>>(ctx, wT + WT_O, b_o, out, DIMX, DIMX, DIMX, DIMX);
}

// round 13
// speedup vs baseline: 1.5353x; 1.5353x over previous
#include <cuda_runtime.h>
#include <cstdint>

#define DIMX   1024
#define NH     16
#define HDIM   64
#define LAT    128
#define QRANK  256
#define BATCH  4
#define SEQ    2048
#define MTOT   (BATCH*SEQ)   // 8192

// ---------------- scratch (device globals: no allocation allowed) -----------
__device__ float g_xtf[(size_t)MTOT * DIMX];         // tf32-rounded x
__device__ float g_cq [(size_t)MTOT * 384];          // [kv_latent | qc] fused
__device__ float g_kv [(size_t)MTOT * 2 * DIMX];     // [K | V] per row
__device__ float g_q  [(size_t)MTOT * DIMX];
__device__ float g_ctx[(size_t)MTOT * DIMX];
__device__ float g_vt [(size_t)BATCH * DIMX * SEQ];  // V^T per batch: [b][d][s]
__device__ float g_wT [1966080];                     // transposed+rounded weights
__device__ float g_bias[384];                        // [b_kvc | b_qc]

#define WT_KVC 0          // [128][1024]
#define WT_QC  131072     // [256][1024]
#define WT_KVU 393216     // [2048][128]
#define WT_QU  655360     // [1024][256]
#define WT_O   917504     // [1024][1024]

// ---------------- helpers ----------------------------------------------------
__device__ __forceinline__ unsigned f2tf(float x){
    unsigned r; asm("cvt.rna.tf32.f32 %0, %1;" : "=r"(r) : "f"(x)); return r;
}
__device__ __forceinline__ float f2tff(float x){ return __uint_as_float(f2tf(x)); }
__device__ __forceinline__ void ldsm4(unsigned* r, unsigned a){
    asm volatile("ldmatrix.sync.aligned.m8n8.x4.shared.b16 {%0,%1,%2,%3}, [%4];"
        : "=r"(r[0]), "=r"(r[1]), "=r"(r[2]), "=r"(r[3]) : "r"(a));
}
__device__ __forceinline__ void mma8(float* c, const unsigned* a, const unsigned* b){
    asm volatile("mma.sync.aligned.m16n8k8.row.col.f32.tf32.tf32.f32 "
        "{%0,%1,%2,%3}, {%4,%5,%6,%7}, {%8,%9}, {%0,%1,%2,%3};"
        : "+f"(c[0]), "+f"(c[1]), "+f"(c[2]), "+f"(c[3])
        : "r"(a[0]), "r"(a[1]), "r"(a[2]), "r"(a[3]), "r"(b[0]), "r"(b[1]));
}
__device__ __forceinline__ void cpa16(unsigned d, const void* s){
    asm volatile("cp.async.cg.shared.global [%0], [%1], 16;" :: "r"(d), "l"(s));
}
__device__ __forceinline__ void cpa_commit(){ asm volatile("cp.async.commit_group;"); }
template<int N> __device__ __forceinline__ void cpa_wait(){
    asm volatile("cp.async.wait_group %0;" :: "n"(N));
}

// swizzled float-index: tile row stride 32 floats (8 chunks of 16B)
#define SWZ32(r,c) (((r)<<5) + ((((c) ^ ((r)&7)) & 7) << 2))
// tile row stride 64 floats (16 chunks)
#define SWZ64(r,c) (((r)<<6) + (((((c)&8) | (((c) ^ (r)) & 7))) << 2))

// 0.125 * log2(e): folds the 1/sqrt(64) score scale into exp2
#define SM_C 0.18033688011112042f

// ---------------- elementwise tf32 rounding of x -----------------------------
__global__ void cvt_tf32_kernel(const float* __restrict__ in, float* __restrict__ out, int n4)
{
    int i = blockIdx.x*blockDim.x + threadIdx.x;
    for (; i < n4; i += gridDim.x*blockDim.x){
        float4 v = ((const float4*)in)[i];
        ((float4*)out)[i] = make_float4(f2tff(v.x), f2tff(v.y), f2tff(v.z), f2tff(v.w));
    }
}

__global__ void concat_bias_kernel(const float* __restrict__ b1, const float* __restrict__ b2,
                                   float* __restrict__ o)
{
    int t = threadIdx.x;
    o[t] = (t < 128) ? b1[t] : b2[t-128];
}

// ---------------- batched transpose + tf32 round ----------------------------
__global__ void transpose_kernel(const float* __restrict__ in, float* __restrict__ out,
                                 int R, int C, int ics, size_t ibs, size_t obs)
{
    __shared__ float t[32][33];
    const float* ib = in  + blockIdx.z * ibs;
    float*       ob = out + blockIdx.z * obs;
    int r0 = blockIdx.y * 32, c0 = blockIdx.x * 32;
    int tx = threadIdx.x, ty = threadIdx.y;
#pragma unroll
    for (int i = 0; i < 32; i += 8)
        t[ty + i][tx] = ib[(size_t)(r0 + ty + i) * ics + c0 + tx];
    __syncthreads();
#pragma unroll
    for (int i = 0; i < 32; i += 8)
        ob[(size_t)(c0 + ty + i) * R + r0 + tx] = f2tff(t[tx][ty + i]);
}

// ---------------- tf32 mma GEMM, 3-stage cp.async pipeline -------------------
// C[.,N] = A @ Bt^T + bias. A lda-strided, Bt compact [N][K]. Operands already
// tf32-rounded in gmem. BM=BN=128, BK=32, 256 threads, warp tile 64x32.
template<int ROUND>
__global__ __launch_bounds__(256)
void gemm_mma(const float* __restrict__ A, const float* __restrict__ Bt,
              const float* __restrict__ bias, float* __restrict__ C,
              int N, int K, int lda, int ldc)
{
    extern __shared__ float sm[];
    float* As = sm;            // 3 stages x 4096 floats
    float* Bs = sm + 3*4096;
    const int tid  = threadIdx.x;
    const int lane = tid & 31, warp = tid >> 5;
    const int wm = warp >> 2, wn = warp & 3;
    const int m0 = blockIdx.y * 128, n0 = blockIdx.x * 128;
    const unsigned sA = (unsigned)__cvta_generic_to_shared(As);
    const unsigned sB = (unsigned)__cvta_generic_to_shared(Bs);
    const int lrow = tid >> 3, lc4 = tid & 7;
    const int g = lane >> 2, t4 = lane & 3;
    const int ar = lane & 15, asel = lane >> 4;

    auto load_stage = [&](int st, int k0){
#pragma unroll
        for (int i = 0; i < 4; i++){
            int r = lrow + 32*i;
            cpa16(sA + 4*(st*4096 + SWZ32(r, lc4)), A  + (size_t)(m0 + r)*lda + k0 + 4*lc4);
            cpa16(sB + 4*(st*4096 + SWZ32(r, lc4)), Bt + (size_t)(n0 + r)*K   + k0 + 4*lc4);
        }
        cpa_commit();
    };

    const int T = K >> 5;
    load_stage(0, 0);
    if (T > 1) load_stage(1, 32);

    float cacc[4][4][4];
#pragma unroll
    for (int i = 0; i < 4; i++)
#pragma unroll
        for (int j = 0; j < 4; j++)
#pragma unroll
            for (int v = 0; v < 4; v++) cacc[i][j][v] = 0.f;

    for (int it = 0; it < T; it++){
        if (it + 1 < T) cpa_wait<1>(); else cpa_wait<0>();
        __syncthreads();
        if (it + 2 < T) load_stage((it+2)%3, 32*(it+2));
        const int so = (it%3)*4096;
#pragma unroll
        for (int kk = 0; kk < 4; kk++){
            unsigned af[4][4];
#pragma unroll
            for (int mi = 0; mi < 4; mi++)
                ldsm4(af[mi], sA + 4*(so + SWZ32(64*wm + 16*mi + ar, 2*kk + asel)));
            unsigned bt[2][4];
#pragma unroll
            for (int p = 0; p < 2; p++){
                int brow = 32*wn + 8*(2*p + (lane >> 4)) + (lane & 7);
                int bch  = 2*kk + ((lane >> 3) & 1);
                ldsm4(bt[p], sB + 4*(so + SWZ32(brow, bch)));
            }
#pragma unroll
            for (int mi = 0; mi < 4; mi++)
#pragma unroll
                for (int nj = 0; nj < 4; nj++)
                    mma8(cacc[mi][nj], af[mi], &bt[nj >> 1][2*(nj & 1)]);
        }
        __syncthreads();
    }
    // epilogue: += bias; optionally round to tf32 for downstream MMA consumers
#pragma unroll
    for (int mi = 0; mi < 4; mi++){
        int row = m0 + 64*wm + 16*mi + g;
#pragma unroll
        for (int nj = 0; nj < 4; nj++){
            int col = n0 + 32*wn + 8*nj + 2*t4;
            float2 b2 = *(const float2*)(bias + col);
            float v0 = cacc[mi][nj][0] + b2.x, v1 = cacc[mi][nj][1] + b2.y;
            float v2 = cacc[mi][nj][2] + b2.x, v3 = cacc[mi][nj][3] + b2.y;
            if (ROUND){ v0=f2tff(v0); v1=f2tff(v1); v2=f2tff(v2); v3=f2tff(v3); }
            *(float2*)(C + (size_t)row*ldc + col)       = make_float2(v0, v1);
            *(float2*)(C + (size_t)(row + 8)*ldc + col) = make_float2(v2, v3);
        }
    }
}

// ---------------- tf32 mma flash attention (causal, hd=64) ------------------
// 256 threads = 8 warps; warp w owns q rows 16w..16w+15. BM=128, BN=64.
// K/V double-buffered via cp.async; Q smem buffer reused for P.
// NOTE: no min-blocks clause — forcing 2 CTAs/SM caps regs at 128 and spills
// the accumulators (R11: +268us). 1 CTA/SM with full registers is faster.
__global__ __launch_bounds__(256)
void flash_mma(const float* __restrict__ Qm, const float* __restrict__ KVm,
               const float* __restrict__ Vt, float* __restrict__ Om)
{
    extern __shared__ float sm[];
    float* sQP = sm;              // 128*64 = 8192 floats
    float* sK  = sm + 8192;       // 2 stages x 4096
    float* sV  = sm + 16384;      // 2 stages x 4096
    const int tid  = threadIdx.x;
    const int lane = tid & 31, w = tid >> 5;
    const int g = lane >> 2, t4 = lane & 3;
    const int qt = (gridDim.x - 1) - blockIdx.x;   // largest-work blocks first
    const int q0 = qt << 7;
    const int h  = blockIdx.y;
    const int b  = blockIdx.z;

    const unsigned sQPa = (unsigned)__cvta_generic_to_shared(sQP);
    const unsigned sKa  = (unsigned)__cvta_generic_to_shared(sK);
    const unsigned sVa  = (unsigned)__cvta_generic_to_shared(sV);

    const float* Qg = Qm  + ((size_t)(b*SEQ + q0))*DIMX + h*HDIM;
    const float* Kg = KVm + ((size_t)(b*SEQ))*(2*DIMX)  + h*HDIM;
    const float* Vg = Vt  + ((size_t)(b*DIMX + h*HDIM))*SEQ;

    auto load_kv = [&](int st, int k0){
#pragma unroll
        for (int i = 0; i < 4; i++){
            int lin = tid + (i << 8);
            int r = lin >> 4, c4 = lin & 15;
            cpa16(sKa + 4*(st*4096 + SWZ64(r, c4)), Kg + (size_t)(k0 + r)*(2*DIMX) + (c4 << 2));
            cpa16(sVa + 4*(st*4096 + SWZ64(r, c4)), Vg + (size_t)r*SEQ + k0 + (c4 << 2));
        }
        cpa_commit();
    };

    // Q tile; already tf32 in gmem
#pragma unroll
    for (int i = 0; i < 8; i++){
        int lin = tid + (i << 8);
        int r = lin >> 4, c4 = lin & 15;
        cpa16(sQPa + 4*SWZ64(r, c4), Qg + (size_t)r*DIMX + (c4 << 2));
    }
    cpa_commit();
    load_kv(0, 0);

    cpa_wait<1>();       // Q group complete (KV0 may still be in flight)
    __syncthreads();

    // Q fragments -> registers (16 rows x 64 d per warp)
    unsigned qf[8][4];
#pragma unroll
    for (int kk = 0; kk < 8; kk++)
        ldsm4(qf[kk], sQPa + 4*SWZ64(16*w + (lane & 15), 2*kk + (lane >> 4)));

    float m_i[2] = {-1e30f, -1e30f}, l_i[2] = {0.f, 0.f};
    float oacc[8][4];
#pragma unroll
    for (int j = 0; j < 8; j++)
#pragma unroll
        for (int v = 0; v < 4; v++) oacc[j][v] = 0.f;

    const int row0 = q0 + 16*w + g;
    const int nt = 2*qt + 2;
    for (int kt = 0; kt < nt; kt++){
        const int k0 = kt << 6;
        cpa_wait<0>();
        __syncthreads();     // all warps done with previous stage + P/Q buffer
        if (kt + 1 < nt) load_kv((kt+1) & 1, (kt+1) << 6);
        const int so = (kt & 1) * 4096;

        // S = Q K^T : warp tile 16 x 64 (raw scores; 1/8 scale folded into exp2)
        float sacc[8][4];
#pragma unroll
        for (int j = 0; j < 8; j++)
#pragma unroll
            for (int v = 0; v < 4; v++) sacc[j][v] = 0.f;
#pragma unroll
        for (int kk = 0; kk < 8; kk++){
            unsigned bt[4][4];
#pragma unroll
            for (int p = 0; p < 4; p++){
                int brow = 8*(2*p + (lane >> 4)) + (lane & 7);
                int bch  = 2*kk + ((lane >> 3) & 1);
                ldsm4(bt[p], sKa + 4*(so + SWZ64(brow, bch)));
            }
#pragma unroll
            for (int j = 0; j < 8; j++)
                mma8(sacc[j], qf[kk], &bt[j >> 1][2*(j & 1)]);
        }

        // causal mask (only tiles crossing this warp's rows)
        if (k0 + 63 > row0){
#pragma unroll
            for (int j = 0; j < 8; j++){
                int c = k0 + 8*j + 2*t4;
                if (c     > row0)     sacc[j][0] = -1e30f;
                if (c + 1 > row0)     sacc[j][1] = -1e30f;
                if (c     > row0 + 8) sacc[j][2] = -1e30f;
                if (c + 1 > row0 + 8) sacc[j][3] = -1e30f;
            }
        }

        // online softmax per row-half (rows row0, row0+8), reduce over 4 lanes.
        // weights = exp2((s - m) * SM_C): score scale + log2(e) in one constant.
#pragma unroll
        for (int hf = 0; hf < 2; hf++){
            float mx = -1e30f;
#pragma unroll
            for (int j = 0; j < 8; j++)
                mx = fmaxf(mx, fmaxf(sacc[j][2*hf], sacc[j][2*hf + 1]));
            mx = fmaxf(mx, __shfl_xor_sync(0xffffffffu, mx, 1));
            mx = fmaxf(mx, __shfl_xor_sync(0xffffffffu, mx, 2));
            float mn = fmaxf(m_i[hf], mx);
            float al = exp2f((m_i[hf] - mn) * SM_C);
            m_i[hf] = mn;
            float rs = 0.f;
#pragma unroll
            for (int j = 0; j < 8; j++){
                sacc[j][2*hf]     = exp2f((sacc[j][2*hf]     - mn) * SM_C);
                sacc[j][2*hf + 1] = exp2f((sacc[j][2*hf + 1] - mn) * SM_C);
                rs += sacc[j][2*hf] + sacc[j][2*hf + 1];
            }
            rs += __shfl_xor_sync(0xffffffffu, rs, 1);
            rs += __shfl_xor_sync(0xffffffffu, rs, 2);
            l_i[hf] = l_i[hf]*al + rs;
#pragma unroll
            for (int j = 0; j < 8; j++){
                oacc[j][2*hf]     *= al;
                oacc[j][2*hf + 1] *= al;
            }
        }

        // write P (tf32) into sQP rows 16w..16w+15 (per-warp private rows)
#pragma unroll
        for (int j = 0; j < 8; j++){
            int col = 8*j + 2*t4;
            int ch = col >> 2, wi = col & 3;
            uint2 p0 = make_uint2(f2tf(sacc[j][0]), f2tf(sacc[j][1]));
            uint2 p1 = make_uint2(f2tf(sacc[j][2]), f2tf(sacc[j][3]));
            *(uint2*)(sQP + SWZ64(16*w + g,     ch) + wi) = p0;
            *(uint2*)(sQP + SWZ64(16*w + g + 8, ch) + wi) = p1;
        }
        __syncwarp();

        // O += P @ V
#pragma unroll
        for (int kk = 0; kk < 8; kk++){
            unsigned pf[4];
            ldsm4(pf, sQPa + 4*SWZ64(16*w + (lane & 15), 2*kk + (lane >> 4)));
            unsigned bt[4][4];
#pragma unroll
            for (int p = 0; p < 4; p++){
                int brow = 8*(2*p + (lane >> 4)) + (lane & 7);
                int bch  = 2*kk + ((lane >> 3) & 1);
                ldsm4(bt[p], sVa + 4*(so + SWZ64(brow, bch)));
            }
#pragma unroll
            for (int j = 0; j < 8; j++)
                mma8(oacc[j], pf, &bt[j >> 1][2*(j & 1)]);
        }
    }

    // epilogue: normalize, round to tf32 (consumed as MMA A by final GEMM)
    float inv0 = 1.0f / l_i[0], inv1 = 1.0f / l_i[1];
    float* Og = Om + ((size_t)(b*SEQ + q0 + 16*w + g))*DIMX + h*HDIM;
#pragma unroll
    for (int j = 0; j < 8; j++){
        int col = 8*j + 2*t4;
        *(float2*)(Og + col)          = make_float2(f2tff(oacc[j][0]*inv0), f2tff(oacc[j][1]*inv0));
        *(float2*)(Og + 8*DIMX + col) = make_float2(f2tff(oacc[j][2]*inv1), f2tff(oacc[j][3]*inv1));
    }
}

// ---------------- launch -----------------------------------------------------
extern "C" void kernel_launch(void* const* d_in, const int* in_sizes, int n_in,
                              void* d_out, int out_size)
{
    (void)in_sizes; (void)n_in; (void)out_size;
    const float* x     = (const float*)d_in[0];
    // d_in[1] = mask (causal by construction; handled analytically)
    const float* w_kvc = (const float*)d_in[2];
    const float* b_kvc = (const float*)d_in[3];
    const float* w_kvu = (const float*)d_in[4];
    const float* b_kvu = (const float*)d_in[5];
    const float* w_qc  = (const float*)d_in[6];
    const float* b_qc  = (const float*)d_in[7];
    const float* w_qu  = (const float*)d_in[8];
    const float* b_qu  = (const float*)d_in[9];
    const float* w_o   = (const float*)d_in[10];
    const float* b_o   = (const float*)d_in[11];
    float* out = (float*)d_out;

    float *xtf, *cq, *kv, *q, *ctx, *vt, *wT, *bias;
    cudaGetSymbolAddress((void**)&xtf,  g_xtf);
    cudaGetSymbolAddress((void**)&cq,   g_cq);
    cudaGetSymbolAddress((void**)&kv,   g_kv);
    cudaGetSymbolAddress((void**)&q,    g_q);
    cudaGetSymbolAddress((void**)&ctx,  g_ctx);
    cudaGetSymbolAddress((void**)&vt,   g_vt);
    cudaGetSymbolAddress((void**)&wT,   g_wT);
    cudaGetSymbolAddress((void**)&bias, g_bias);

    const int SMEM = 96*1024;
    cudaFuncSetAttribute(gemm_mma<0>, cudaFuncAttributeMaxDynamicSharedMemorySize, SMEM);
    cudaFuncSetAttribute(gemm_mma<1>, cudaFuncAttributeMaxDynamicSharedMemorySize, SMEM);
    cudaFuncSetAttribute(flash_mma,   cudaFuncAttributeMaxDynamicSharedMemorySize, SMEM);

    dim3 tb(32, 8);
    cvt_tf32_kernel<<<2048, 256>>>(x, xtf, MTOT*DIMX/4);
    transpose_kernel<<<dim3(128/32, 1024/32), tb>>>(w_kvc, wT + WT_KVC, 1024, 128, 128, 0, 0);
    transpose_kernel<<<dim3(256/32, 1024/32), tb>>>(w_qc,  wT + WT_QC,  1024, 256, 256, 0, 0);
    transpose_kernel<<<dim3(2048/32, 128/32), tb>>>(w_kvu, wT + WT_KVU, 128, 2048, 2048, 0, 0);
    concat_bias_kernel<<<1, 384>>>(b_kvc, b_qc, bias);
    // fused [kv_latent | qc] = x @ [w_kvc | w_qc]^T + bias   [8192,384]
    gemm_mma<1><<<dim3(3, 64), 256, SMEM>>>(xtf, wT + WT_KVC, bias, cq, 384, DIMX, DIMX, 384);
    transpose_kernel<<<dim3(1024/32, 256/32), tb>>>(w_qu,  wT + WT_QU,  256, 1024, 1024, 0, 0);
    transpose_kernel<<<dim3(1024/32, 1024/32), tb>>>(w_o,  wT + WT_O,  1024, 1024, 1024, 0, 0);
    // kv = kv_latent @ w_kvu^T + b_kvu                       [8192,2048]
    gemm_mma<1><<<dim3(16, 64), 256, SMEM>>>(cq, wT + WT_KVU, b_kvu, kv, 2*DIMX, LAT, 384, 2*DIMX);
    // V^T per batch
    transpose_kernel<<<dim3(1024/32, 2048/32, BATCH), tb>>>(
        kv + DIMX, vt, SEQ, DIMX, 2*DIMX, (size_t)SEQ*2*DIMX, (size_t)DIMX*SEQ);
    // Q = qc @ w_qu^T + b_qu                                 [8192,1024]
    gemm_mma<1><<<dim3(8, 64), 256, SMEM>>>(cq + 128, wT + WT_QU, b_qu, q, DIMX, QRANK, 384, DIMX);
    // attention
    flash_mma<<<dim3(SEQ/128, NH, BATCH), 256, SMEM>>>(q, kv, vt, ctx);
    // out = ctx @ w_o^T + b_o (fp32 epilogue)                [8192,1024]
    gemm_mma<0><<<dim3(8, 64), 256, SMEM>>>(ctx, wT + WT_O, b_o, out, DIMX, DIMX, DIMX, DIMX);
}

// round 14
// speedup vs baseline: 2.4851x; 1.6187x over previous
#include <cuda_runtime.h>
#include <cuda_fp16.h>
#include <cstdint>

#define DIMX   1024
#define NH     16
#define HDIM   64
#define LAT    128
#define QRANK  256
#define BATCH  4
#define SEQ    2048
#define MTOT   (BATCH*SEQ)   // 8192

// ---------------- scratch (device globals: no allocation allowed) -----------
__device__ __half g_xh [(size_t)MTOT * DIMX];         // fp16 x
__device__ __half g_cq [(size_t)MTOT * 384];          // [kv_latent | qc] fused
__device__ __half g_kv [(size_t)MTOT * 2 * DIMX];     // [K | V] per row
__device__ __half g_q  [(size_t)MTOT * DIMX];
__device__ __half g_ctx[(size_t)MTOT * DIMX];
__device__ __half g_vt [(size_t)BATCH * DIMX * SEQ];  // V^T per batch: [b][d][s]
__device__ __half g_wT [1966080];                     // transposed fp16 weights
__device__ float  g_bias[384];                        // [b_kvc | b_qc]

#define WT_KVC 0          // [128][1024]
#define WT_QC  131072     // [256][1024]
#define WT_KVU 393216     // [2048][128]
#define WT_QU  655360     // [1024][256]
#define WT_O   917504     // [1024][1024]

// ---------------- helpers ----------------------------------------------------
__device__ __forceinline__ void ldsm4(unsigned* r, unsigned a){
    asm volatile("ldmatrix.sync.aligned.m8n8.x4.shared.b16 {%0,%1,%2,%3}, [%4];"
        : "=r"(r[0]), "=r"(r[1]), "=r"(r[2]), "=r"(r[3]) : "r"(a));
}
// fp16 mma, fp32 accumulate: same precision as tf32 (11-bit significand), 2x rate
__device__ __forceinline__ void mma16(float* c, const unsigned* a, const unsigned* b){
    asm volatile("mma.sync.aligned.m16n8k16.row.col.f32.f16.f16.f32 "
        "{%0,%1,%2,%3}, {%4,%5,%6,%7}, {%8,%9}, {%0,%1,%2,%3};"
        : "+f"(c[0]), "+f"(c[1]), "+f"(c[2]), "+f"(c[3])
        : "r"(a[0]), "r"(a[1]), "r"(a[2]), "r"(a[3]), "r"(b[0]), "r"(b[1]));
}
__device__ __forceinline__ void cpa16(unsigned d, const void* s){
    asm volatile("cp.async.cg.shared.global [%0], [%1], 16;" :: "r"(d), "l"(s));
}
__device__ __forceinline__ void cpa_commit(){ asm volatile("cp.async.commit_group;"); }
template<int N> __device__ __forceinline__ void cpa_wait(){
    asm volatile("cp.async.wait_group %0;" :: "n"(N));
}

// half-index into a 64-half (128B) row tile, XOR-chunk swizzle (8x16B chunks)
#define SWZH(r,c) (((r)<<6) + ((((c) ^ ((r)&7)) & 7) << 3))

// 0.125 * log2(e): folds the 1/sqrt(64) score scale into exp2
#define SM_C 0.18033688011112042f

// ---------------- x -> fp16 ---------------------------------------------------
__global__ void cvt_h_kernel(const float* __restrict__ in, __half* __restrict__ out, int n2)
{
    int i = blockIdx.x*blockDim.x + threadIdx.x;
    for (; i < n2; i += gridDim.x*blockDim.x){
        float2 v = ((const float2*)in)[i];
        ((half2*)out)[i] = __floats2half2_rn(v.x, v.y);
    }
}

__global__ void concat_bias_kernel(const float* __restrict__ b1, const float* __restrict__ b2,
                                   float* __restrict__ o)
{
    int t = threadIdx.x;
    o[t] = (t < 128) ? b1[t] : b2[t-128];
}

// ---------------- weight transpose: float in -> half out ---------------------
__global__ void transpose_fh_kernel(const float* __restrict__ in, __half* __restrict__ out,
                                    int R, int C, int ics)
{
    __shared__ float t[32][33];
    int r0 = blockIdx.y * 32, c0 = blockIdx.x * 32;
    int tx = threadIdx.x, ty = threadIdx.y;
#pragma unroll
    for (int i = 0; i < 32; i += 8)
        t[ty + i][tx] = in[(size_t)(r0 + ty + i) * ics + c0 + tx];
    __syncthreads();
#pragma unroll
    for (int i = 0; i < 32; i += 8)
        out[(size_t)(c0 + ty + i) * R + r0 + tx] = __float2half(t[tx][ty + i]);
}

// ---------------- V transpose: half in -> half out ---------------------------
__global__ void transpose_hh_kernel(const __half* __restrict__ in, __half* __restrict__ out,
                                    int R, int ics, size_t ibs, size_t obs)
{
    __shared__ __half t[32][34];
    const __half* ib = in  + blockIdx.z * ibs;
    __half*       ob = out + blockIdx.z * obs;
    int r0 = blockIdx.y * 32, c0 = blockIdx.x * 32;
    int tx = threadIdx.x, ty = threadIdx.y;
#pragma unroll
    for (int i = 0; i < 32; i += 8)
        t[ty + i][tx] = ib[(size_t)(r0 + ty + i) * ics + c0 + tx];
    __syncthreads();
#pragma unroll
    for (int i = 0; i < 32; i += 8)
        ob[(size_t)(c0 + ty + i) * R + r0 + tx] = t[tx][ty + i];
}

// ---------------- fp16 mma GEMM, 3-stage cp.async pipeline -------------------
// C[.,*] = A @ Bt^T + bias. A lda-strided [M,K] half, Bt compact [N][K] half.
// BM=BN=128, BK=64 halfs (128B rows), 256 threads, warp tile 64x32.
// HOUT=1: write __half (feeds downstream mma); HOUT=0: write float (final out).
template<int HOUT>
__global__ __launch_bounds__(256)
void gemm_h(const __half* __restrict__ A, const __half* __restrict__ Bt,
            const float* __restrict__ bias, void* __restrict__ Cv,
            int K, int lda, int ldc)
{
    extern __shared__ __half smh[];
    const int tid  = threadIdx.x;
    const int lane = tid & 31, warp = tid >> 5;
    const int wm = warp >> 2, wn = warp & 3;
    const int m0 = blockIdx.y * 128, n0 = blockIdx.x * 128;
    const unsigned sb = (unsigned)__cvta_generic_to_shared(smh);
    // stage layout (bytes): [A 16KB | B 16KB] x 3
    const int g = lane >> 2, t4 = lane & 3;
    const int ar = lane & 15, asel = lane >> 4;

    auto load_stage = [&](int st, int k0){
        unsigned ab = sb + st*32768u, bb = ab + 16384u;
#pragma unroll
        for (int i = 0; i < 4; i++){
            int idx = tid + (i << 8);            // 0..1023
            int r = idx >> 3, c = idx & 7;
            cpa16(ab + 2*SWZH(r, c), A  + (size_t)(m0 + r)*lda + k0 + 8*c);
            cpa16(bb + 2*SWZH(r, c), Bt + (size_t)(n0 + r)*K   + k0 + 8*c);
        }
        cpa_commit();
    };

    const int T = K >> 6;
    load_stage(0, 0);
    if (T > 1) load_stage(1, 64);

    float cacc[4][4][4];
#pragma unroll
    for (int i = 0; i < 4; i++)
#pragma unroll
        for (int j = 0; j < 4; j++)
#pragma unroll
            for (int v = 0; v < 4; v++) cacc[i][j][v] = 0.f;

    for (int it = 0; it < T; it++){
        if (it + 1 < T) cpa_wait<1>(); else cpa_wait<0>();
        __syncthreads();
        if (it + 2 < T) load_stage((it+2)%3, 64*(it+2));
        unsigned ab = sb + (it%3)*32768u, bb = ab + 16384u;
#pragma unroll
        for (int kk = 0; kk < 4; kk++){          // 4 x K=16 steps per 64-chunk
            unsigned af[4][4];
#pragma unroll
            for (int mi = 0; mi < 4; mi++)
                ldsm4(af[mi], ab + 2*SWZH(64*wm + 16*mi + ar, 2*kk + asel));
            unsigned bt[2][4];
#pragma unroll
            for (int p = 0; p < 2; p++){
                int brow = 32*wn + 16*p + 8*(lane >> 4) + (lane & 7);
                int bch  = 2*kk + ((lane >> 3) & 1);
                ldsm4(bt[p], bb + 2*SWZH(brow, bch));
            }
#pragma unroll
            for (int mi = 0; mi < 4; mi++)
#pragma unroll
                for (int nj = 0; nj < 4; nj++)
                    mma16(cacc[mi][nj], af[mi], &bt[nj >> 1][2*(nj & 1)]);
        }
        __syncthreads();
    }
    // epilogue: += bias (fp32), write half2 or float2
#pragma unroll
    for (int mi = 0; mi < 4; mi++){
        int row = m0 + 64*wm + 16*mi + g;
#pragma unroll
        for (int nj = 0; nj < 4; nj++){
            int col = n0 + 32*wn + 8*nj + 2*t4;
            float2 b2 = *(const float2*)(bias + col);
            float v0 = cacc[mi][nj][0] + b2.x, v1 = cacc[mi][nj][1] + b2.y;
            float v2 = cacc[mi][nj][2] + b2.x, v3 = cacc[mi][nj][3] + b2.y;
            if (HOUT){
                __half* C = (__half*)Cv;
                *(half2*)(C + (size_t)row*ldc + col)       = __floats2half2_rn(v0, v1);
                *(half2*)(C + (size_t)(row + 8)*ldc + col) = __floats2half2_rn(v2, v3);
            } else {
                float* C = (float*)Cv;
                *(float2*)(C + (size_t)row*ldc + col)       = make_float2(v0, v1);
                *(float2*)(C + (size_t)(row + 8)*ldc + col) = make_float2(v2, v3);
            }
        }
    }
}

// ---------------- fp16 mma flash attention (causal, hd=64) ------------------
// 256 threads = 8 warps; warp w owns q rows 16w..16w+15. BM=128, BN=64.
// K/V double-buffered via cp.async; Q smem buffer reused for P. All half.
__global__ __launch_bounds__(256)
void flash_h(const __half* __restrict__ Qm, const __half* __restrict__ KVm,
             const __half* __restrict__ Vt, __half* __restrict__ Om)
{
    extern __shared__ __half smh[];
    __half* sQP = smh;                 // 128 x 64 halfs = 16KB (Q, then P)
    const unsigned sQPb = (unsigned)__cvta_generic_to_shared(sQP);
    const unsigned sKb  = sQPb + 16384u;   // 2 stages x 8KB
    const unsigned sVb  = sQPb + 32768u;   // 2 stages x 8KB
    const int tid  = threadIdx.x;
    const int lane = tid & 31, w = tid >> 5;
    const int g = lane >> 2, t4 = lane & 3;
    const int qt = (gridDim.x - 1) - blockIdx.x;   // largest-work blocks first
    const int q0 = qt << 7;
    const int h  = blockIdx.y;
    const int b  = blockIdx.z;

    const __half* Qg = Qm  + ((size_t)(b*SEQ + q0))*DIMX + h*HDIM;
    const __half* Kg = KVm + ((size_t)(b*SEQ))*(2*DIMX)  + h*HDIM;
    const __half* Vg = Vt  + ((size_t)(b*DIMX + h*HDIM))*SEQ;

    auto load_kv = [&](int st, int k0){
#pragma unroll
        for (int i = 0; i < 2; i++){
            int idx = tid + (i << 8);            // 0..511
            int r = idx >> 3, c = idx & 7;
            cpa16(sKb + st*8192u + 2*SWZH(r, c), Kg + (size_t)(k0 + r)*(2*DIMX) + 8*c);
            cpa16(sVb + st*8192u + 2*SWZH(r, c), Vg + (size_t)r*SEQ + k0 + 8*c);
        }
        cpa_commit();
    };

    // Q tile: 128 rows x 8 chunks
#pragma unroll
    for (int i = 0; i < 4; i++){
        int idx = tid + (i << 8);
        int r = idx >> 3, c = idx & 7;
        cpa16(sQPb + 2*SWZH(r, c), Qg + (size_t)r*DIMX + 8*c);
    }
    cpa_commit();
    load_kv(0, 0);

    cpa_wait<1>();       // Q group complete (KV0 may still be in flight)
    __syncthreads();

    // Q fragments -> registers (16 rows x 64 d per warp, 4 K=16 steps)
    unsigned qf[4][4];
#pragma unroll
    for (int kk = 0; kk < 4; kk++)
        ldsm4(qf[kk], sQPb + 2*SWZH(16*w + (lane & 15), 2*kk + (lane >> 4)));

    float m_i[2] = {-1e30f, -1e30f}, l_i[2] = {0.f, 0.f};
    float oacc[8][4];
#pragma unroll
    for (int j = 0; j < 8; j++)
#pragma unroll
        for (int v = 0; v < 4; v++) oacc[j][v] = 0.f;

    const int row0 = q0 + 16*w + g;
    const int nt = 2*qt + 2;
    for (int kt = 0; kt < nt; kt++){
        const int k0 = kt << 6;
        cpa_wait<0>();
        __syncthreads();     // all warps done with previous stage + P buffer
        if (kt + 1 < nt) load_kv((kt+1) & 1, (kt+1) << 6);
        const unsigned so = (unsigned)((kt & 1) * 8192);

        // S = Q K^T : warp tile 16 x 64 (raw scores; 1/8 folded into exp2)
        float sacc[8][4];
#pragma unroll
        for (int j = 0; j < 8; j++)
#pragma unroll
            for (int v = 0; v < 4; v++) sacc[j][v] = 0.f;
#pragma unroll
        for (int kk = 0; kk < 4; kk++){
            unsigned bt[4][4];
#pragma unroll
            for (int p = 0; p < 4; p++){
                int brow = 16*p + 8*(lane >> 4) + (lane & 7);
                int bch  = 2*kk + ((lane >> 3) & 1);
                ldsm4(bt[p], sKb + so + 2*SWZH(brow, bch));
            }
#pragma unroll
            for (int j = 0; j < 8; j++)
                mma16(sacc[j], qf[kk], &bt[j >> 1][2*(j & 1)]);
        }

        // causal mask (only tiles crossing this warp's rows)
        if (k0 + 63 > row0){
#pragma unroll
            for (int j = 0; j < 8; j++){
                int c = k0 + 8*j + 2*t4;
                if (c     > row0)     sacc[j][0] = -1e30f;
                if (c + 1 > row0)     sacc[j][1] = -1e30f;
                if (c     > row0 + 8) sacc[j][2] = -1e30f;
                if (c + 1 > row0 + 8) sacc[j][3] = -1e30f;
            }
        }

        // online softmax per row-half (rows row0, row0+8), reduce over 4 lanes
#pragma unroll
        for (int hf = 0; hf < 2; hf++){
            float mx = -1e30f;
#pragma unroll
            for (int j = 0; j < 8; j++)
                mx = fmaxf(mx, fmaxf(sacc[j][2*hf], sacc[j][2*hf + 1]));
            mx = fmaxf(mx, __shfl_xor_sync(0xffffffffu, mx, 1));
            mx = fmaxf(mx, __shfl_xor_sync(0xffffffffu, mx, 2));
            float mn = fmaxf(m_i[hf], mx);
            float al = exp2f((m_i[hf] - mn) * SM_C);
            m_i[hf] = mn;
            float rs = 0.f;
#pragma unroll
            for (int j = 0; j < 8; j++){
                sacc[j][2*hf]     = exp2f((sacc[j][2*hf]     - mn) * SM_C);
                sacc[j][2*hf + 1] = exp2f((sacc[j][2*hf + 1] - mn) * SM_C);
                rs += sacc[j][2*hf] + sacc[j][2*hf + 1];
            }
            rs += __shfl_xor_sync(0xffffffffu, rs, 1);
            rs += __shfl_xor_sync(0xffffffffu, rs, 2);
            l_i[hf] = l_i[hf]*al + rs;
#pragma unroll
            for (int j = 0; j < 8; j++){
                oacc[j][2*hf]     *= al;
                oacc[j][2*hf + 1] *= al;
            }
        }

        // write P (fp16) into sQP rows 16w..16w+15 (per-warp private rows)
#pragma unroll
        for (int j = 0; j < 8; j++){
            int r0w = 16*w + g;
            *(half2*)(sQP + SWZH(r0w,     j) + 2*t4) = __floats2half2_rn(sacc[j][0], sacc[j][1]);
            *(half2*)(sQP + SWZH(r0w + 8, j) + 2*t4) = __floats2half2_rn(sacc[j][2], sacc[j][3]);
        }
        __syncwarp();

        // O += P @ V
#pragma unroll
        for (int kk = 0; kk < 4; kk++){
            unsigned pf[4];
            ldsm4(pf, sQPb + 2*SWZH(16*w + (lane & 15), 2*kk + (lane >> 4)));
            unsigned bt[4][4];
#pragma unroll
            for (int p = 0; p < 4; p++){
                int brow = 16*p + 8*(lane >> 4) + (lane & 7);
                int bch  = 2*kk + ((lane >> 3) & 1);
                ldsm4(bt[p], sVb + so + 2*SWZH(brow, bch));
            }
#pragma unroll
            for (int j = 0; j < 8; j++)
                mma16(oacc[j], pf, &bt[j >> 1][2*(j & 1)]);
        }
    }

    // epilogue: normalize, write ctx (fp16, feeds final GEMM as A operand)
    float inv0 = 1.0f / l_i[0], inv1 = 1.0f / l_i[1];
    __half* Og = Om + ((size_t)(b*SEQ + q0 + 16*w + g))*DIMX + h*HDIM;
#pragma unroll
    for (int j = 0; j < 8; j++){
        int col = 8*j + 2*t4;
        *(half2*)(Og + col)          = __floats2half2_rn(oacc[j][0]*inv0, oacc[j][1]*inv0);
        *(half2*)(Og + 8*DIMX + col) = __floats2half2_rn(oacc[j][2]*inv1, oacc[j][3]*inv1);
    }
}

// ---------------- launch -----------------------------------------------------
extern "C" void kernel_launch(void* const* d_in, const int* in_sizes, int n_in,
                              void* d_out, int out_size)
{
    (void)in_sizes; (void)n_in; (void)out_size;
    const float* x     = (const float*)d_in[0];
    // d_in[1] = mask (causal by construction; handled analytically)
    const float* w_kvc = (const float*)d_in[2];
    const float* b_kvc = (const float*)d_in[3];
    const float* w_kvu = (const float*)d_in[4];
    const float* b_kvu = (const float*)d_in[5];
    const float* w_qc  = (const float*)d_in[6];
    const float* b_qc  = (const float*)d_in[7];
    const float* w_qu  = (const float*)d_in[8];
    const float* b_qu  = (const float*)d_in[9];
    const float* w_o   = (const float*)d_in[10];
    const float* b_o   = (const float*)d_in[11];
    float* out = (float*)d_out;

    __half *xh, *cq, *kv, *q, *ctx, *vt, *wT;
    float *bias;
    cudaGetSymbolAddress((void**)&xh,   g_xh);
    cudaGetSymbolAddress((void**)&cq,   g_cq);
    cudaGetSymbolAddress((void**)&kv,   g_kv);
    cudaGetSymbolAddress((void**)&q,    g_q);
    cudaGetSymbolAddress((void**)&ctx,  g_ctx);
    cudaGetSymbolAddress((void**)&vt,   g_vt);
    cudaGetSymbolAddress((void**)&wT,   g_wT);
    cudaGetSymbolAddress((void**)&bias, g_bias);

    const int SMEM_G = 3*32768;     // 96KB: 3 stages x (A 16KB + B 16KB)
    const int SMEM_F = 48*1024;     // QP 16KB + K 2x8KB + V 2x8KB
    cudaFuncSetAttribute(gemm_h<0>, cudaFuncAttributeMaxDynamicSharedMemorySize, SMEM_G);
    cudaFuncSetAttribute(gemm_h<1>, cudaFuncAttributeMaxDynamicSharedMemorySize, SMEM_G);
    cudaFuncSetAttribute(flash_h,   cudaFuncAttributeMaxDynamicSharedMemorySize, SMEM_F);

    dim3 tb(32, 8);
    cvt_h_kernel<<<2048, 256>>>(x, xh, MTOT*DIMX/2);
    transpose_fh_kernel<<<dim3(128/32, 1024/32), tb>>>(w_kvc, wT + WT_KVC, 1024, 128, 128);
    transpose_fh_kernel<<<dim3(256/32, 1024/32), tb>>>(w_qc,  wT + WT_QC,  1024, 256, 256);
    transpose_fh_kernel<<<dim3(2048/32, 128/32), tb>>>(w_kvu, wT + WT_KVU, 128, 2048, 2048);
    concat_bias_kernel<<<1, 384>>>(b_kvc, b_qc, bias);
    // fused [kv_latent | qc] = x @ [w_kvc | w_qc]^T + bias   [8192,384]
    gemm_h<1><<<dim3(3, 64), 256, SMEM_G>>>(xh, wT + WT_KVC, bias, cq, DIMX, DIMX, 384);
    transpose_fh_kernel<<<dim3(1024/32, 256/32), tb>>>(w_qu, wT + WT_QU, 256, 1024, 1024);
    transpose_fh_kernel<<<dim3(1024/32, 1024/32), tb>>>(w_o, wT + WT_O, 1024, 1024, 1024);
    // kv = kv_latent @ w_kvu^T + b_kvu                       [8192,2048]
    gemm_h<1><<<dim3(16, 64), 256, SMEM_G>>>(cq, wT + WT_KVU, b_kvu, kv, LAT, 384, 2*DIMX);
    // V^T per batch: vt[b][d][s]
    transpose_hh_kernel<<<dim3(1024/32, 2048/32, BATCH), tb>>>(
        kv + DIMX, vt, SEQ, 2*DIMX, (size_t)SEQ*2*DIMX, (size_t)DIMX*SEQ);
    // Q = qc @ w_qu^T + b_qu                                 [8192,1024]
    gemm_h<1><<<dim3(8, 64), 256, SMEM_G>>>(cq + 128, wT + WT_QU, b_qu, q, QRANK, 384, DIMX);
    // attention
    flash_h<<<dim3(SEQ/128, NH, BATCH), 256, SMEM_F>>>(q, kv, vt, ctx);
    // out = ctx @ w_o^T + b_o (fp32 epilogue)                [8192,1024]
    gemm_h<0><<<dim3(8, 64), 256, SMEM_G>>>(ctx, wT + WT_O, b_o, out, DIMX, DIMX, DIMX);
}